// round 1
// baseline (speedup 1.0000x reference)
#include <cuda_runtime.h>
#include <cuda_bf16.h>
#include <math.h>
#include <stdint.h>

#define EMB 1024
#define FF  4096
#define MTOK 8192

// ---------------- scratch (static device globals; no allocation) ----------------
__device__ __nv_bfloat16 g_w1q[FF * EMB];
__device__ __nv_bfloat16 g_w2q[EMB * FF];
__device__ __nv_bfloat16 g_xhi[MTOK * EMB];
__device__ __nv_bfloat16 g_xlo[MTOK * EMB];
__device__ __nv_bfloat16 g_hhi[(size_t)MTOK * FF];
__device__ __nv_bfloat16 g_hlo[(size_t)MTOK * FF];
__device__ double g_part[2][256];
__device__ float  g_scale[2];

// ---------------- absmean (deterministic two-stage fp64 reduction) ----------------
__global__ void absmean_stage1(const float* __restrict__ W, int n, int which) {
    int tid = threadIdx.x;
    double s = 0.0;
    for (int i = blockIdx.x * 256 + tid; i < n; i += 256 * 256)
        s += (double)fabsf(W[i]);
    __shared__ double sm[256];
    sm[tid] = s; __syncthreads();
    for (int o = 128; o > 0; o >>= 1) { if (tid < o) sm[tid] += sm[tid + o]; __syncthreads(); }
    if (tid == 0) g_part[which][blockIdx.x] = sm[0];
}

__global__ void absmean_stage2(int n, int which) {
    int tid = threadIdx.x;
    __shared__ double sm[256];
    sm[tid] = g_part[which][tid]; __syncthreads();
    for (int o = 128; o > 0; o >>= 1) { if (tid < o) sm[tid] += sm[tid + o]; __syncthreads(); }
    if (tid == 0) {
        float mean = (float)(sm[0] / (double)n);
        g_scale[which] = fmaxf(mean, 1e-8f);
    }
}

// ---------------- ternarize: clip(rint(w/scale), -1, 1) -> bf16 (exact) ----------------
__global__ void quantize_kernel(const float* __restrict__ W, int n, int which,
                                __nv_bfloat16* __restrict__ out) {
    float s = g_scale[which];
    for (int i = blockIdx.x * blockDim.x + threadIdx.x; i < n; i += gridDim.x * blockDim.x) {
        float q = rintf(W[i] / s);          // rint = round-half-even, matches jnp.round
        q = fminf(1.0f, fmaxf(-1.0f, q));
        out[i] = __float2bfloat16(q);
    }
}

// ---------------- fp32 -> (bf16 hi, bf16 lo) split ----------------
__global__ void split_kernel(const float* __restrict__ X, int n,
                             __nv_bfloat16* __restrict__ hi, __nv_bfloat16* __restrict__ lo) {
    for (int i = blockIdx.x * blockDim.x + threadIdx.x; i < n; i += gridDim.x * blockDim.x) {
        float f = X[i];
        __nv_bfloat16 h = __float2bfloat16(f);
        hi[i] = h;
        lo[i] = __float2bfloat16(f - __bfloat162float(h));
    }
}

// ---------------- GEMM: C[M,N] = (Ahi+Alo)[M,K] * B[N,K]^T  (+bias, opt. GELU-split) ----------------
#define BM 128
#define BN 128
#define BK 64
#define STAGE_BYTES 49152   // Ahi 16KB + Alo 16KB + B 16KB
#define SMEM_BYTES  (2 * STAGE_BYTES)

__device__ __forceinline__ void cp16(uint32_t dst, const void* src) {
    asm volatile("cp.async.cg.shared.global [%0], [%1], 16;\n" :: "r"(dst), "l"(src));
}
__device__ __forceinline__ void ldsm4(uint32_t& r0, uint32_t& r1, uint32_t& r2, uint32_t& r3,
                                      uint32_t a) {
    asm volatile("ldmatrix.sync.aligned.m8n8.x4.shared.b16 {%0,%1,%2,%3}, [%4];"
                 : "=r"(r0), "=r"(r1), "=r"(r2), "=r"(r3) : "r"(a));
}
__device__ __forceinline__ void mma16816(float* c, const uint32_t* a, const uint32_t* b) {
    asm volatile("mma.sync.aligned.m16n8k16.row.col.f32.bf16.bf16.f32 "
                 "{%0,%1,%2,%3}, {%4,%5,%6,%7}, {%8,%9}, {%0,%1,%2,%3};"
                 : "+f"(c[0]), "+f"(c[1]), "+f"(c[2]), "+f"(c[3])
                 : "r"(a[0]), "r"(a[1]), "r"(a[2]), "r"(a[3]), "r"(b[0]), "r"(b[1]));
}

template <int K>
__device__ __forceinline__ void load_tile(uint32_t stage_base,
                                          const __nv_bfloat16* gAhi,
                                          const __nv_bfloat16* gAlo,
                                          const __nv_bfloat16* gB, int tid) {
    const int chunk = tid & 7;       // 16B chunk within 128B row
    const int r0 = tid >> 3;         // 0..31
#pragma unroll
    for (int i = 0; i < 4; i++) {
        int row = r0 + i * 32;
        uint32_t so = (uint32_t)(row * 128 + ((chunk ^ (row & 7)) << 4));  // SW128-style swizzle
        size_t go = (size_t)row * K + chunk * 8;
        cp16(stage_base + so,           gAhi + go);
        cp16(stage_base + 16384u + so,  gAlo + go);
        cp16(stage_base + 32768u + so,  gB + go);
    }
    asm volatile("cp.async.commit_group;\n" ::: "memory");
}

template <int N, int K, bool FUSE_GELU>
__global__ void __launch_bounds__(256, 2)
ffn_gemm(const __nv_bfloat16* __restrict__ Ahi, const __nv_bfloat16* __restrict__ Alo,
         const __nv_bfloat16* __restrict__ B,   const float* __restrict__ bias,
         __nv_bfloat16* __restrict__ Ohi, __nv_bfloat16* __restrict__ Olo,
         float* __restrict__ Of) {
    extern __shared__ char smem[];
    const int tid  = threadIdx.x;
    const int lane = tid & 31;
    const int warp = tid >> 5;
    const int wm = (warp & 1) * 64;    // warp tile 64(M) x 32(N), warps 2x4
    const int wn = (warp >> 1) * 32;
    const int bm = blockIdx.y * BM;
    const int bn = blockIdx.x * BN;

    const uint32_t sbase = (uint32_t)__cvta_generic_to_shared(smem);

    const __nv_bfloat16* gAhi = Ahi + (size_t)bm * K;
    const __nv_bfloat16* gAlo = Alo + (size_t)bm * K;
    const __nv_bfloat16* gB0  = B + (size_t)bn * K;

    float c[4][4][4];
#pragma unroll
    for (int i = 0; i < 4; i++)
#pragma unroll
        for (int j = 0; j < 4; j++)
#pragma unroll
            for (int k = 0; k < 4; k++) c[i][j][k] = 0.0f;

    const int KT = K / BK;
    load_tile<K>(sbase, gAhi, gAlo, gB0, tid);

    // per-lane ldmatrix address components
    const int lrow  = lane & 15;        // A: row within 16-row tile
    const int lhalf = lane >> 4;        // A: k half (0/1)
    const int boff  = (lane >> 4) << 3; // B: +8 n rows for octs 2,3
    const int bkh   = (lane >> 3) & 1;  // B: k half per oct pair

    for (int kt = 0; kt < KT; kt++) {
        if (kt + 1 < KT) {
            load_tile<K>(sbase + ((kt + 1) & 1) * STAGE_BYTES,
                         gAhi + (kt + 1) * BK, gAlo + (kt + 1) * BK, gB0 + (kt + 1) * BK, tid);
            asm volatile("cp.async.wait_group 1;\n" ::: "memory");
        } else {
            asm volatile("cp.async.wait_group 0;\n" ::: "memory");
        }
        __syncthreads();

        const uint32_t st  = sbase + (kt & 1) * STAGE_BYTES;
        const uint32_t aHi = st, aLo = st + 16384u, aB = st + 32768u;

#pragma unroll
        for (int ks = 0; ks < BK / 16; ks++) {
            uint32_t bfr[4][2];
#pragma unroll
            for (int p = 0; p < 2; p++) {
                int nrow = wn + p * 16 + boff + (lane & 7);
                int cb = ks * 32 + (bkh << 4);
                uint32_t addr = aB + (uint32_t)(nrow * 128 + ((((cb >> 4) ^ (nrow & 7))) << 4));
                uint32_t t0, t1, t2, t3;
                ldsm4(t0, t1, t2, t3, addr);
                bfr[2 * p][0] = t0; bfr[2 * p][1] = t1;
                bfr[2 * p + 1][0] = t2; bfr[2 * p + 1][1] = t3;
            }
            uint32_t afr[4][4];
#pragma unroll
            for (int mi = 0; mi < 4; mi++) {
                int arow = wm + mi * 16 + lrow;
                int cb = ks * 32 + (lhalf << 4);
                uint32_t addr = aHi + (uint32_t)(arow * 128 + ((((cb >> 4) ^ (arow & 7))) << 4));
                ldsm4(afr[mi][0], afr[mi][1], afr[mi][2], afr[mi][3], addr);
            }
#pragma unroll
            for (int mi = 0; mi < 4; mi++)
#pragma unroll
                for (int ni = 0; ni < 4; ni++) mma16816(c[mi][ni], afr[mi], bfr[ni]);
#pragma unroll
            for (int mi = 0; mi < 4; mi++) {
                int arow = wm + mi * 16 + lrow;
                int cb = ks * 32 + (lhalf << 4);
                uint32_t addr = aLo + (uint32_t)(arow * 128 + ((((cb >> 4) ^ (arow & 7))) << 4));
                ldsm4(afr[mi][0], afr[mi][1], afr[mi][2], afr[mi][3], addr);
            }
#pragma unroll
            for (int mi = 0; mi < 4; mi++)
#pragma unroll
                for (int ni = 0; ni < 4; ni++) mma16816(c[mi][ni], afr[mi], bfr[ni]);
        }
        __syncthreads();
    }

    // ---------------- epilogue ----------------
    const int g = lane >> 2, t = lane & 3;
#pragma unroll
    for (int mi = 0; mi < 4; mi++) {
#pragma unroll
        for (int ni = 0; ni < 4; ni++) {
            int m0 = bm + wm + mi * 16 + g;
            int n0 = bn + wn + ni * 8 + 2 * t;
            float bv0 = __ldg(bias + n0), bv1 = __ldg(bias + n0 + 1);
            float* cc = c[mi][ni];
            if (FUSE_GELU) {
#pragma unroll
                for (int half = 0; half < 2; half++) {
                    int m = m0 + half * 8;
                    float v0 = cc[2 * half + 0] + bv0;
                    float v1 = cc[2 * half + 1] + bv1;
                    float gl0 = 0.5f * v0 * (1.0f + erff(v0 * 0.70710678118654752f));
                    float gl1 = 0.5f * v1 * (1.0f + erff(v1 * 0.70710678118654752f));
                    __nv_bfloat16 h0 = __float2bfloat16(gl0);
                    __nv_bfloat16 h1 = __float2bfloat16(gl1);
                    __nv_bfloat162 hp; hp.x = h0; hp.y = h1;
                    __nv_bfloat162 lp;
                    lp.x = __float2bfloat16(gl0 - __bfloat162float(h0));
                    lp.y = __float2bfloat16(gl1 - __bfloat162float(h1));
                    *(__nv_bfloat162*)(Ohi + (size_t)m * N + n0) = hp;
                    *(__nv_bfloat162*)(Olo + (size_t)m * N + n0) = lp;
                }
            } else {
#pragma unroll
                for (int half = 0; half < 2; half++) {
                    int m = m0 + half * 8;
                    float2 v;
                    v.x = cc[2 * half + 0] + bv0;
                    v.y = cc[2 * half + 1] + bv1;
                    *(float2*)(Of + (size_t)m * N + n0) = v;
                }
            }
        }
    }
}

// ---------------- launch ----------------
extern "C" void kernel_launch(void* const* d_in, const int* in_sizes, int n_in,
                              void* d_out, int out_size) {
    (void)in_sizes; (void)n_in; (void)out_size;
    const float* x  = (const float*)d_in[0];
    const float* W1 = (const float*)d_in[1];
    const float* b1 = (const float*)d_in[2];
    const float* W2 = (const float*)d_in[3];
    const float* b2 = (const float*)d_in[4];
    float* out = (float*)d_out;

    __nv_bfloat16 *w1q, *w2q, *xhi, *xlo, *hhi, *hlo;
    cudaGetSymbolAddress((void**)&w1q, g_w1q);
    cudaGetSymbolAddress((void**)&w2q, g_w2q);
    cudaGetSymbolAddress((void**)&xhi, g_xhi);
    cudaGetSymbolAddress((void**)&xlo, g_xlo);
    cudaGetSymbolAddress((void**)&hhi, g_hhi);
    cudaGetSymbolAddress((void**)&hlo, g_hlo);

    absmean_stage1<<<256, 256>>>(W1, FF * EMB, 0);
    absmean_stage1<<<256, 256>>>(W2, EMB * FF, 1);
    absmean_stage2<<<1, 256>>>(FF * EMB, 0);
    absmean_stage2<<<1, 256>>>(EMB * FF, 1);
    quantize_kernel<<<1024, 256>>>(W1, FF * EMB, 0, w1q);
    quantize_kernel<<<1024, 256>>>(W2, EMB * FF, 1, w2q);
    split_kernel<<<1024, 256>>>(x, MTOK * EMB, xhi, xlo);

    cudaFuncSetAttribute(ffn_gemm<FF, EMB, true>,
                         cudaFuncAttributeMaxDynamicSharedMemorySize, SMEM_BYTES);
    cudaFuncSetAttribute(ffn_gemm<EMB, FF, false>,
                         cudaFuncAttributeMaxDynamicSharedMemorySize, SMEM_BYTES);

    ffn_gemm<FF, EMB, true><<<dim3(FF / BN, MTOK / BM), 256, SMEM_BYTES>>>(
        xhi, xlo, w1q, b1, hhi, hlo, nullptr);
    ffn_gemm<EMB, FF, false><<<dim3(EMB / BN, MTOK / BM), 256, SMEM_BYTES>>>(
        hhi, hlo, w2q, b2, nullptr, nullptr, out);
}

// round 3
// speedup vs baseline: 1.5471x; 1.5471x over previous
#include <cuda_runtime.h>
#include <cuda_fp16.h>
#include <math.h>
#include <stdint.h>

#define EMB 1024
#define FF  4096
#define MTOK 8192

// ---------------- scratch (static device globals; no allocation) ----------------
__device__ __half g_w1q[FF * EMB];
__device__ __half g_w2q[EMB * FF];
__device__ __half g_xh[MTOK * EMB];
__device__ __half g_h[(size_t)MTOK * FF];
__device__ double g_part[2][256];
__device__ float  g_scale[2];

// ---------------- absmean (deterministic two-stage fp64 reduction) ----------------
__global__ void absmean_stage1(const float* __restrict__ W, int n, int which) {
    int tid = threadIdx.x;
    double s = 0.0;
    for (int i = blockIdx.x * 256 + tid; i < n; i += 256 * 256)
        s += (double)fabsf(W[i]);
    __shared__ double sm[256];
    sm[tid] = s; __syncthreads();
    for (int o = 128; o > 0; o >>= 1) { if (tid < o) sm[tid] += sm[tid + o]; __syncthreads(); }
    if (tid == 0) g_part[which][blockIdx.x] = sm[0];
}

__global__ void absmean_stage2(int n, int which) {
    int tid = threadIdx.x;
    __shared__ double sm[256];
    sm[tid] = g_part[which][tid]; __syncthreads();
    for (int o = 128; o > 0; o >>= 1) { if (tid < o) sm[tid] += sm[tid + o]; __syncthreads(); }
    if (tid == 0) {
        float mean = (float)(sm[0] / (double)n);
        g_scale[which] = fmaxf(mean, 1e-8f);
    }
}

// ---------------- ternarize: clip(rint(w/scale),-1,1) -> fp16 (exact) ----------------
__global__ void quantize_kernel(const float4* __restrict__ W, int n4, int which,
                                __half2* __restrict__ out) {
    float s = 1.0f / g_scale[which];
    for (int i = blockIdx.x * blockDim.x + threadIdx.x; i < n4; i += gridDim.x * blockDim.x) {
        float4 w = W[i];
        float q0 = fminf(1.0f, fmaxf(-1.0f, rintf(w.x * s)));
        float q1 = fminf(1.0f, fmaxf(-1.0f, rintf(w.y * s)));
        float q2 = fminf(1.0f, fmaxf(-1.0f, rintf(w.z * s)));
        float q3 = fminf(1.0f, fmaxf(-1.0f, rintf(w.w * s)));
        out[2 * i]     = __halves2half2(__float2half_rn(q0), __float2half_rn(q1));
        out[2 * i + 1] = __halves2half2(__float2half_rn(q2), __float2half_rn(q3));
    }
}

// ---------------- fp32 -> fp16 activation convert ----------------
__global__ void tohalf_kernel(const float4* __restrict__ X, int n4, __half2* __restrict__ o) {
    for (int i = blockIdx.x * blockDim.x + threadIdx.x; i < n4; i += gridDim.x * blockDim.x) {
        float4 f = X[i];
        o[2 * i]     = __halves2half2(__float2half_rn(f.x), __float2half_rn(f.y));
        o[2 * i + 1] = __halves2half2(__float2half_rn(f.z), __float2half_rn(f.w));
    }
}

// ================= HMMA GEMM: C[M,N] = A[M,K] * B[N,K]^T =================
#define BM 128
#define BK 64
#define NS 3

__device__ __forceinline__ void cp16(uint32_t dst, const void* src) {
    asm volatile("cp.async.cg.shared.global [%0], [%1], 16;\n" :: "r"(dst), "l"(src));
}
__device__ __forceinline__ void ldsm4(uint32_t& r0, uint32_t& r1, uint32_t& r2, uint32_t& r3,
                                      uint32_t a) {
    asm volatile("ldmatrix.sync.aligned.m8n8.x4.shared.b16 {%0,%1,%2,%3}, [%4];"
                 : "=r"(r0), "=r"(r1), "=r"(r2), "=r"(r3) : "r"(a));
}
__device__ __forceinline__ void mma16816(float* c, const uint32_t* a, const uint32_t* b) {
    asm volatile("mma.sync.aligned.m16n8k16.row.col.f32.f16.f16.f32 "
                 "{%0,%1,%2,%3}, {%4,%5,%6,%7}, {%8,%9}, {%0,%1,%2,%3};"
                 : "+f"(c[0]), "+f"(c[1]), "+f"(c[2]), "+f"(c[3])
                 : "r"(a[0]), "r"(a[1]), "r"(a[2]), "r"(a[3]), "r"(b[0]), "r"(b[1]));
}

// stage layout: A (16KB) then B (BN_*128 bytes); SW128-style 16B-chunk swizzle
template <int BN_, int K>
__device__ __forceinline__ void load_stage(uint32_t sb, const __half* __restrict__ gA,
                                           const __half* __restrict__ gB, int tid) {
    const int chunk = tid & 7;     // 16B chunk within 128B row
    const int r0 = tid >> 3;       // 0..31
#pragma unroll
    for (int i = 0; i < 4; i++) {
        int row = r0 + i * 32;     // 0..127
        uint32_t so = (uint32_t)(row * 128 + ((chunk ^ (row & 7)) << 4));
        cp16(sb + so, gA + (size_t)row * K + chunk * 8);
    }
#pragma unroll
    for (int i = 0; i < BN_ / 32; i++) {
        int row = r0 + i * 32;     // 0..BN_-1
        uint32_t so = (uint32_t)(row * 128 + ((chunk ^ (row & 7)) << 4));
        cp16(sb + 16384u + so, gB + (size_t)row * K + chunk * 8);
    }
    asm volatile("cp.async.commit_group;\n" ::: "memory");
}

template <int BN_, int N, int K, bool FUSE_GELU>
__global__ void __launch_bounds__(256)
ffn_gemm_h(const __half* __restrict__ A, const __half* __restrict__ B,
           const float* __restrict__ bias, __half* __restrict__ Oh,
           float* __restrict__ Of) {
    constexpr int NF = BN_ / 32;                 // n8 frags per warp (warp n-tile = BN_/4)
    constexpr uint32_t STAGE = 16384u + BN_ * 128u;
    extern __shared__ char smem[];
    const uint32_t sb = (uint32_t)__cvta_generic_to_shared(smem);
    const int tid = threadIdx.x, lane = tid & 31, warp = tid >> 5;
    const int wm = (warp & 1) * 64;
    const int wn = (warp >> 1) * (BN_ / 4);
    const int bm = blockIdx.y * BM, bn = blockIdx.x * BN_;

    const __half* gA = A + (size_t)bm * K;
    const __half* gB = B + (size_t)bn * K;

    float c[4][NF][4];
#pragma unroll
    for (int i = 0; i < 4; i++)
#pragma unroll
        for (int j = 0; j < NF; j++)
#pragma unroll
            for (int k = 0; k < 4; k++) c[i][j][k] = 0.0f;

    const int KT = K / BK;
#pragma unroll
    for (int s = 0; s < NS - 1; s++)
        load_stage<BN_, K>(sb + s * STAGE, gA + s * BK, gB + s * BK, tid);

    const int lrow  = lane & 15;        // A row within 16-row tile
    const int lhalf = lane >> 4;        // A k half
    const int boff  = (lane >> 4) << 3; // B +8 rows for octs 2,3
    const int bkh   = (lane >> 3) & 1;  // B k half per oct pair

    for (int kt = 0; kt < KT; kt++) {
        const int nk = kt + NS - 1;
        if (nk < KT)
            load_stage<BN_, K>(sb + (nk % NS) * STAGE, gA + (size_t)nk * BK,
                               gB + (size_t)nk * BK, tid);
        else
            asm volatile("cp.async.commit_group;\n" ::: "memory");
        asm volatile("cp.async.wait_group %0;\n" :: "n"(NS - 1) : "memory");
        __syncthreads();

        const uint32_t aA = sb + (kt % NS) * STAGE;
        const uint32_t aB = aA + 16384u;

#pragma unroll
        for (int ks = 0; ks < BK / 16; ks++) {
            uint32_t bfr[NF][2];
#pragma unroll
            for (int p = 0; p < NF / 2; p++) {
                int nrow = wn + p * 16 + boff + (lane & 7);
                int cb = ks * 32 + (bkh << 4);
                uint32_t addr = aB + (uint32_t)(nrow * 128 + ((((cb >> 4) ^ (nrow & 7))) << 4));
                uint32_t t0, t1, t2, t3;
                ldsm4(t0, t1, t2, t3, addr);
                bfr[2 * p][0] = t0; bfr[2 * p][1] = t1;
                bfr[2 * p + 1][0] = t2; bfr[2 * p + 1][1] = t3;
            }
            uint32_t afr[4][4];
#pragma unroll
            for (int mi = 0; mi < 4; mi++) {
                int arow = wm + mi * 16 + lrow;
                int cb = ks * 32 + (lhalf << 4);
                uint32_t addr = aA + (uint32_t)(arow * 128 + ((((cb >> 4) ^ (arow & 7))) << 4));
                ldsm4(afr[mi][0], afr[mi][1], afr[mi][2], afr[mi][3], addr);
            }
#pragma unroll
            for (int mi = 0; mi < 4; mi++)
#pragma unroll
                for (int ni = 0; ni < NF; ni++) mma16816(c[mi][ni], afr[mi], bfr[ni]);
        }
        __syncthreads();
    }

    // ---------------- epilogue ----------------
    const int g = lane >> 2, t = lane & 3;
#pragma unroll
    for (int mi = 0; mi < 4; mi++) {
#pragma unroll
        for (int ni = 0; ni < NF; ni++) {
            int m0 = bm + wm + mi * 16 + g;
            int n0 = bn + wn + ni * 8 + 2 * t;
            float bv0 = __ldg(bias + n0), bv1 = __ldg(bias + n0 + 1);
            float* cc = c[mi][ni];
#pragma unroll
            for (int half = 0; half < 2; half++) {
                int m = m0 + half * 8;
                float v0 = cc[2 * half + 0] + bv0;
                float v1 = cc[2 * half + 1] + bv1;
                if (FUSE_GELU) {
                    float gl0 = 0.5f * v0 * (1.0f + erff(v0 * 0.70710678118654752f));
                    float gl1 = 0.5f * v1 * (1.0f + erff(v1 * 0.70710678118654752f));
                    *(__half2*)(Oh + (size_t)m * N + n0) =
                        __halves2half2(__float2half_rn(gl0), __float2half_rn(gl1));
                } else {
                    float2 v; v.x = v0; v.y = v1;
                    *(float2*)(Of + (size_t)m * N + n0) = v;
                }
            }
        }
    }
}

// ---------------- launch ----------------
extern "C" void kernel_launch(void* const* d_in, const int* in_sizes, int n_in,
                              void* d_out, int out_size) {
    (void)in_sizes; (void)n_in; (void)out_size;
    const float* x  = (const float*)d_in[0];
    const float* W1 = (const float*)d_in[1];
    const float* b1 = (const float*)d_in[2];
    const float* W2 = (const float*)d_in[3];
    const float* b2 = (const float*)d_in[4];
    float* out = (float*)d_out;

    __half *w1q, *w2q, *xh, *h;
    cudaGetSymbolAddress((void**)&w1q, g_w1q);
    cudaGetSymbolAddress((void**)&w2q, g_w2q);
    cudaGetSymbolAddress((void**)&xh, g_xh);
    cudaGetSymbolAddress((void**)&h, g_h);

    absmean_stage1<<<256, 256>>>(W1, FF * EMB, 0);
    absmean_stage1<<<256, 256>>>(W2, EMB * FF, 1);
    absmean_stage2<<<1, 256>>>(FF * EMB, 0);
    absmean_stage2<<<1, 256>>>(EMB * FF, 1);
    quantize_kernel<<<512, 256>>>((const float4*)W1, FF * EMB / 4, 0, (__half2*)w1q);
    quantize_kernel<<<512, 256>>>((const float4*)W2, EMB * FF / 4, 1, (__half2*)w2q);
    tohalf_kernel<<<512, 256>>>((const float4*)x, MTOK * EMB / 4, (__half2*)xh);

    // GEMM1: BN=256 (16x64 CTAs), GEMM2: BN=128 (8x64 CTAs)
    constexpr int SMEM1 = NS * (16384 + 256 * 128);   // 147456
    constexpr int SMEM2 = NS * (16384 + 128 * 128);   //  98304
    cudaFuncSetAttribute(ffn_gemm_h<256, FF, EMB, true>,
                         cudaFuncAttributeMaxDynamicSharedMemorySize, SMEM1);
    cudaFuncSetAttribute(ffn_gemm_h<128, EMB, FF, false>,
                         cudaFuncAttributeMaxDynamicSharedMemorySize, SMEM2);

    ffn_gemm_h<256, FF, EMB, true><<<dim3(FF / 256, MTOK / BM), 256, SMEM1>>>(
        xh, w1q, b1, h, nullptr);
    ffn_gemm_h<128, EMB, FF, false><<<dim3(EMB / 128, MTOK / BM), 256, SMEM2>>>(
        h, w2q, b2, nullptr, out);
}

// round 4
// speedup vs baseline: 1.6852x; 1.0893x over previous
#include <cuda_runtime.h>
#include <cuda_fp16.h>
#include <math.h>
#include <stdint.h>

#define EMB 1024
#define FF  4096
#define MTOK 8192

// ---------------- scratch (static device globals; no allocation) ----------------
__device__ __half g_w1q[FF * EMB];
__device__ __half g_w2q[EMB * FF];
__device__ __half g_xh[MTOK * EMB];
__device__ __half g_h[(size_t)MTOK * FF];
__device__ double g_part[2][256];

// ---------------- absmean stage1 for both weights in one launch ----------------
__global__ void absmean_both(const float* __restrict__ W1, const float* __restrict__ W2, int n) {
    int which = blockIdx.x >> 8;
    int blk = blockIdx.x & 255;
    const float* W = which ? W2 : W1;
    int tid = threadIdx.x;
    double s = 0.0;
    for (int i = blk * 256 + tid; i < n; i += 256 * 256)
        s += (double)fabsf(W[i]);
    __shared__ double sm[256];
    sm[tid] = s; __syncthreads();
    for (int o = 128; o > 0; o >>= 1) { if (tid < o) sm[tid] += sm[tid + o]; __syncthreads(); }
    if (tid == 0) g_part[which][blk] = sm[0];
}

// ---------------- ternarize both weights; scale reduced in-kernel ----------------
__global__ void quantize_both(const float4* __restrict__ W1, const float4* __restrict__ W2,
                              int n4, __half2* __restrict__ o1, __half2* __restrict__ o2) {
    const int which = blockIdx.y;
    const float4* W = which ? W2 : W1;
    __half2* out = which ? o2 : o1;
    int tid = threadIdx.x;
    __shared__ double sm[256];
    __shared__ float ssc;
    sm[tid] = g_part[which][tid]; __syncthreads();
    for (int o = 128; o > 0; o >>= 1) { if (tid < o) sm[tid] += sm[tid + o]; __syncthreads(); }
    if (tid == 0) {
        float mean = (float)(sm[0] / (double)(n4 * 4));
        ssc = 1.0f / fmaxf(mean, 1e-8f);
    }
    __syncthreads();
    const float s = ssc;
    for (int i = blockIdx.x * blockDim.x + tid; i < n4; i += gridDim.x * blockDim.x) {
        float4 w = W[i];
        float q0 = fminf(1.0f, fmaxf(-1.0f, rintf(w.x * s)));
        float q1 = fminf(1.0f, fmaxf(-1.0f, rintf(w.y * s)));
        float q2 = fminf(1.0f, fmaxf(-1.0f, rintf(w.z * s)));
        float q3 = fminf(1.0f, fmaxf(-1.0f, rintf(w.w * s)));
        out[2 * i]     = __halves2half2(__float2half_rn(q0), __float2half_rn(q1));
        out[2 * i + 1] = __halves2half2(__float2half_rn(q2), __float2half_rn(q3));
    }
}

// ---------------- fp32 -> fp16 activation convert ----------------
__global__ void tohalf_kernel(const float4* __restrict__ X, int n4, __half2* __restrict__ o) {
    for (int i = blockIdx.x * blockDim.x + threadIdx.x; i < n4; i += gridDim.x * blockDim.x) {
        float4 f = X[i];
        o[2 * i]     = __halves2half2(__float2half_rn(f.x), __float2half_rn(f.y));
        o[2 * i + 1] = __halves2half2(__float2half_rn(f.z), __float2half_rn(f.w));
    }
}

// ================= HMMA GEMM: C[M,N] = A[M,K] * B[N,K]^T =================
#define BK 64
#define NS 3

__device__ __forceinline__ void cp16(uint32_t dst, const void* src) {
    asm volatile("cp.async.cg.shared.global [%0], [%1], 16;\n" :: "r"(dst), "l"(src));
}
__device__ __forceinline__ void ldsm4(uint32_t& r0, uint32_t& r1, uint32_t& r2, uint32_t& r3,
                                      uint32_t a) {
    asm volatile("ldmatrix.sync.aligned.m8n8.x4.shared.b16 {%0,%1,%2,%3}, [%4];"
                 : "=r"(r0), "=r"(r1), "=r"(r2), "=r"(r3) : "r"(a));
}
__device__ __forceinline__ void mma16816(float* c, const uint32_t* a, const uint32_t* b) {
    asm volatile("mma.sync.aligned.m16n8k16.row.col.f32.f16.f16.f32 "
                 "{%0,%1,%2,%3}, {%4,%5,%6,%7}, {%8,%9}, {%0,%1,%2,%3};"
                 : "+f"(c[0]), "+f"(c[1]), "+f"(c[2]), "+f"(c[3])
                 : "r"(a[0]), "r"(a[1]), "r"(a[2]), "r"(a[3]), "r"(b[0]), "r"(b[1]));
}

// stage layout: A (BM_*128B) then B (BN_*128B); SW128-style 16B-chunk swizzle
template <int BM_, int BN_, int K>
__device__ __forceinline__ void load_stage(uint32_t sb, const __half* __restrict__ gA,
                                           const __half* __restrict__ gB, int tid) {
    const int chunk = tid & 7;     // 16B chunk within 128B row
    const int r0 = tid >> 3;       // 0..31
#pragma unroll
    for (int i = 0; i < BM_ / 32; i++) {
        int row = r0 + i * 32;
        uint32_t so = (uint32_t)(row * 128 + ((chunk ^ (row & 7)) << 4));
        cp16(sb + so, gA + (size_t)row * K + chunk * 8);
    }
#pragma unroll
    for (int i = 0; i < BN_ / 32; i++) {
        int row = r0 + i * 32;
        uint32_t so = (uint32_t)(row * 128 + ((chunk ^ (row & 7)) << 4));
        cp16(sb + (uint32_t)(BM_ * 128) + so, gB + (size_t)row * K + chunk * 8);
    }
    asm volatile("cp.async.commit_group;\n" ::: "memory");
}

template <int BM_, int BN_, int N, int K, bool FUSE_GELU>
__global__ void __launch_bounds__(256, 2)
ffn_gemm_h(const __half* __restrict__ A, const __half* __restrict__ B,
           const float* __restrict__ bias, __half* __restrict__ Oh,
           float* __restrict__ Of) {
    constexpr int MF = BM_ / 2 / 16;             // m16 frags per warp (warp m-tile = BM_/2)
    constexpr int NF = BN_ / 4 / 8;              // n8 frags per warp (warp n-tile = BN_/4)
    constexpr uint32_t STAGE = (BM_ + BN_) * 128u;
    extern __shared__ char smem[];
    const uint32_t sb = (uint32_t)__cvta_generic_to_shared(smem);
    const int tid = threadIdx.x, lane = tid & 31, warp = tid >> 5;
    const int wm = (warp & 1) * (BM_ / 2);
    const int wn = (warp >> 1) * (BN_ / 4);
    const int bm = blockIdx.y * BM_, bn = blockIdx.x * BN_;

    const __half* gA = A + (size_t)bm * K;
    const __half* gB = B + (size_t)bn * K;

    float c[MF][NF][4];
#pragma unroll
    for (int i = 0; i < MF; i++)
#pragma unroll
        for (int j = 0; j < NF; j++)
#pragma unroll
            for (int k = 0; k < 4; k++) c[i][j][k] = 0.0f;

    const int KT = K / BK;
#pragma unroll
    for (int s = 0; s < NS - 1; s++)
        load_stage<BM_, BN_, K>(sb + s * STAGE, gA + s * BK, gB + s * BK, tid);

    const int lrow  = lane & 15;        // A row within 16-row tile
    const int lhalf = lane >> 4;        // A k half
    const int boff  = (lane >> 4) << 3; // B +8 rows for octs 2,3
    const int bkh   = (lane >> 3) & 1;  // B k half per oct pair

    for (int kt = 0; kt < KT; kt++) {
        // single barrier per iteration: wait for buf kt, sync, then prefetch kt+NS-1
        asm volatile("cp.async.wait_group %0;\n" :: "n"(NS - 2) : "memory");
        __syncthreads();
        const int nk = kt + NS - 1;
        if (nk < KT)
            load_stage<BM_, BN_, K>(sb + (nk % NS) * STAGE, gA + (size_t)nk * BK,
                                    gB + (size_t)nk * BK, tid);
        else
            asm volatile("cp.async.commit_group;\n" ::: "memory");

        const uint32_t aA = sb + (kt % NS) * STAGE;
        const uint32_t aB = aA + (uint32_t)(BM_ * 128);

#pragma unroll
        for (int ks = 0; ks < BK / 16; ks++) {
            uint32_t bfr[NF][2];
#pragma unroll
            for (int p = 0; p < NF / 2; p++) {
                int nrow = wn + p * 16 + boff + (lane & 7);
                int cb = ks * 32 + (bkh << 4);
                uint32_t addr = aB + (uint32_t)(nrow * 128 + ((((cb >> 4) ^ (nrow & 7))) << 4));
                uint32_t t0, t1, t2, t3;
                ldsm4(t0, t1, t2, t3, addr);
                bfr[2 * p][0] = t0; bfr[2 * p][1] = t1;
                bfr[2 * p + 1][0] = t2; bfr[2 * p + 1][1] = t3;
            }
            uint32_t afr[MF][4];
#pragma unroll
            for (int mi = 0; mi < MF; mi++) {
                int arow = wm + mi * 16 + lrow;
                int cb = ks * 32 + (lhalf << 4);
                uint32_t addr = aA + (uint32_t)(arow * 128 + ((((cb >> 4) ^ (arow & 7))) << 4));
                ldsm4(afr[mi][0], afr[mi][1], afr[mi][2], afr[mi][3], addr);
            }
#pragma unroll
            for (int mi = 0; mi < MF; mi++)
#pragma unroll
                for (int ni = 0; ni < NF; ni++) mma16816(c[mi][ni], afr[mi], bfr[ni]);
        }
    }

    // ---------------- epilogue ----------------
    const int g = lane >> 2, t = lane & 3;
#pragma unroll
    for (int mi = 0; mi < MF; mi++) {
#pragma unroll
        for (int ni = 0; ni < NF; ni++) {
            int m0 = bm + wm + mi * 16 + g;
            int n0 = bn + wn + ni * 8 + 2 * t;
            float bv0 = __ldg(bias + n0), bv1 = __ldg(bias + n0 + 1);
            float* cc = c[mi][ni];
#pragma unroll
            for (int half = 0; half < 2; half++) {
                int m = m0 + half * 8;
                float v0 = cc[2 * half + 0] + bv0;
                float v1 = cc[2 * half + 1] + bv1;
                if (FUSE_GELU) {
                    float gl0 = 0.5f * v0 * (1.0f + erff(v0 * 0.70710678118654752f));
                    float gl1 = 0.5f * v1 * (1.0f + erff(v1 * 0.70710678118654752f));
                    *(__half2*)(Oh + (size_t)m * N + n0) =
                        __halves2half2(__float2half_rn(gl0), __float2half_rn(gl1));
                } else {
                    float2 v; v.x = v0; v.y = v1;
                    *(float2*)(Of + (size_t)m * N + n0) = v;
                }
            }
        }
    }
}

// ---------------- launch ----------------
extern "C" void kernel_launch(void* const* d_in, const int* in_sizes, int n_in,
                              void* d_out, int out_size) {
    (void)in_sizes; (void)n_in; (void)out_size;
    const float* x  = (const float*)d_in[0];
    const float* W1 = (const float*)d_in[1];
    const float* b1 = (const float*)d_in[2];
    const float* W2 = (const float*)d_in[3];
    const float* b2 = (const float*)d_in[4];
    float* out = (float*)d_out;

    __half *w1q, *w2q, *xh, *h;
    cudaGetSymbolAddress((void**)&w1q, g_w1q);
    cudaGetSymbolAddress((void**)&w2q, g_w2q);
    cudaGetSymbolAddress((void**)&xh, g_xh);
    cudaGetSymbolAddress((void**)&h, g_h);

    absmean_both<<<512, 256>>>(W1, W2, FF * EMB);
    quantize_both<<<dim3(512, 2), 256>>>((const float4*)W1, (const float4*)W2,
                                         FF * EMB / 4, (__half2*)w1q, (__half2*)w2q);
    tohalf_kernel<<<512, 256>>>((const float4*)x, MTOK * EMB / 4, (__half2*)xh);

    constexpr int SMEM1 = NS * (128 + 128) * 128;   // 98304
    constexpr int SMEM2 = NS * (64 + 128) * 128;    // 73728
    cudaFuncSetAttribute(ffn_gemm_h<128, 128, FF, EMB, true>,
                         cudaFuncAttributeMaxDynamicSharedMemorySize, SMEM1);
    cudaFuncSetAttribute(ffn_gemm_h<64, 128, EMB, FF, false>,
                         cudaFuncAttributeMaxDynamicSharedMemorySize, SMEM2);

    ffn_gemm_h<128, 128, FF, EMB, true><<<dim3(FF / 128, MTOK / 128), 256, SMEM1>>>(
        xh, w1q, b1, h, nullptr);
    ffn_gemm_h<64, 128, EMB, FF, false><<<dim3(EMB / 128, MTOK / 64), 256, SMEM2>>>(
        h, w2q, b2, nullptr, out);
}

// round 5
// speedup vs baseline: 1.7558x; 1.0419x over previous
#include <cuda_runtime.h>
#include <cuda_fp16.h>
#include <math.h>
#include <stdint.h>

#define EMB 1024
#define FF  4096
#define MTOK 8192

// ---------------- scratch (static device globals; no allocation) ----------------
__device__ __half g_w1q[FF * EMB];
__device__ __half g_w2q[EMB * FF];
__device__ __half g_xh[MTOK * EMB];
__device__ __half g_h[(size_t)MTOK * FF];
__device__ double g_part[2][512];

// ---------------- absmean stage1 (vectorized, both weights, one launch) --------
__global__ void absmean_both(const float4* __restrict__ W1, const float4* __restrict__ W2,
                             int n4) {
    int which = blockIdx.x >> 9;          // 512 blocks per weight
    int blk = blockIdx.x & 511;
    const float4* W = which ? W2 : W1;
    int tid = threadIdx.x;
    double s = 0.0;
    for (int i = blk * 256 + tid; i < n4; i += 512 * 256) {
        float4 w = W[i];
        s += (double)((fabsf(w.x) + fabsf(w.y)) + (fabsf(w.z) + fabsf(w.w)));
    }
    __shared__ double sm[256];
    sm[tid] = s; __syncthreads();
    for (int o = 128; o > 0; o >>= 1) { if (tid < o) sm[tid] += sm[tid + o]; __syncthreads(); }
    if (tid == 0) g_part[which][blk] = sm[0];
}

// ---------------- ternarize both weights; scale reduced in-kernel --------------
__global__ void quantize_both(const float4* __restrict__ W1, const float4* __restrict__ W2,
                              int n4, __half2* __restrict__ o1, __half2* __restrict__ o2) {
    const int which = blockIdx.y;
    const float4* W = which ? W2 : W1;
    __half2* out = which ? o2 : o1;
    int tid = threadIdx.x;
    __shared__ double sm[256];
    __shared__ float ssc;
    sm[tid] = g_part[which][tid] + g_part[which][tid + 256];
    __syncthreads();
    for (int o = 128; o > 0; o >>= 1) { if (tid < o) sm[tid] += sm[tid + o]; __syncthreads(); }
    if (tid == 0) {
        float mean = (float)(sm[0] / (double)(n4 * 4));
        ssc = 1.0f / fmaxf(mean, 1e-8f);
    }
    __syncthreads();
    const float s = ssc;
    for (int i = blockIdx.x * blockDim.x + tid; i < n4; i += gridDim.x * blockDim.x) {
        float4 w = W[i];
        float q0 = fminf(1.0f, fmaxf(-1.0f, rintf(w.x * s)));
        float q1 = fminf(1.0f, fmaxf(-1.0f, rintf(w.y * s)));
        float q2 = fminf(1.0f, fmaxf(-1.0f, rintf(w.z * s)));
        float q3 = fminf(1.0f, fmaxf(-1.0f, rintf(w.w * s)));
        out[2 * i]     = __halves2half2(__float2half_rn(q0), __float2half_rn(q1));
        out[2 * i + 1] = __halves2half2(__float2half_rn(q2), __float2half_rn(q3));
    }
}

// ---------------- fp32 -> fp16 activation convert ----------------
__global__ void tohalf_kernel(const float4* __restrict__ X, int n4, __half2* __restrict__ o) {
    for (int i = blockIdx.x * blockDim.x + threadIdx.x; i < n4; i += gridDim.x * blockDim.x) {
        float4 f = X[i];
        o[2 * i]     = __halves2half2(__float2half_rn(f.x), __float2half_rn(f.y));
        o[2 * i + 1] = __halves2half2(__float2half_rn(f.z), __float2half_rn(f.w));
    }
}

// ================= HMMA GEMM: C[M,N] = A[M,K] * B[N,K]^T =================
#define BK 64
#define NS 3

__device__ __forceinline__ void cp16(uint32_t dst, const void* src) {
    asm volatile("cp.async.cg.shared.global [%0], [%1], 16;\n" :: "r"(dst), "l"(src));
}
__device__ __forceinline__ void ldsm4(uint32_t& r0, uint32_t& r1, uint32_t& r2, uint32_t& r3,
                                      uint32_t a) {
    asm volatile("ldmatrix.sync.aligned.m8n8.x4.shared.b16 {%0,%1,%2,%3}, [%4];"
                 : "=r"(r0), "=r"(r1), "=r"(r2), "=r"(r3) : "r"(a));
}
__device__ __forceinline__ void mma16816(float* c, const uint32_t* a, const uint32_t* b) {
    asm volatile("mma.sync.aligned.m16n8k16.row.col.f32.f16.f16.f32 "
                 "{%0,%1,%2,%3}, {%4,%5,%6,%7}, {%8,%9}, {%0,%1,%2,%3};"
                 : "+f"(c[0]), "+f"(c[1]), "+f"(c[2]), "+f"(c[3])
                 : "r"(a[0]), "r"(a[1]), "r"(a[2]), "r"(a[3]), "r"(b[0]), "r"(b[1]));
}

// stage layout: A (BM_*128B) then B (BN_*128B); SW128-style 16B-chunk swizzle
template <int BM_, int BN_, int K>
__device__ __forceinline__ void load_stage(uint32_t sb, const __half* __restrict__ gA,
                                           const __half* __restrict__ gB, int tid) {
    const int chunk = tid & 7;
    const int r0 = tid >> 3;
#pragma unroll
    for (int i = 0; i < BM_ / 32; i++) {
        int row = r0 + i * 32;
        uint32_t so = (uint32_t)(row * 128 + ((chunk ^ (row & 7)) << 4));
        cp16(sb + so, gA + (size_t)row * K + chunk * 8);
    }
#pragma unroll
    for (int i = 0; i < BN_ / 32; i++) {
        int row = r0 + i * 32;
        uint32_t so = (uint32_t)(row * 128 + ((chunk ^ (row & 7)) << 4));
        cp16(sb + (uint32_t)(BM_ * 128) + so, gB + (size_t)row * K + chunk * 8);
    }
    asm volatile("cp.async.commit_group;\n" ::: "memory");
}

template <int BM_, int BN_, int N, int K, bool FUSE_GELU>
__global__ void __launch_bounds__(256, 2)
ffn_gemm_h(const __half* __restrict__ A, const __half* __restrict__ B,
           const float* __restrict__ bias, __half* __restrict__ Oh,
           float* __restrict__ Of) {
    constexpr int MF = BM_ / 2 / 16;             // m16 frags per warp
    constexpr int NF = BN_ / 4 / 8;              // n8 frags per warp
    constexpr uint32_t STAGE = (BM_ + BN_) * 128u;
    extern __shared__ char smem_raw[];
    // force 128-byte alignment so stage bases have bits 0-6 clear (XOR addressing)
    const uint32_t sb = ((uint32_t)__cvta_generic_to_shared(smem_raw) + 127u) & ~127u;
    const int tid = threadIdx.x, lane = tid & 31, warp = tid >> 5;
    const int wm = (warp & 1) * (BM_ / 2);
    const int wn = (warp >> 1) * (BN_ / 4);
    const int bm = blockIdx.y * BM_, bn = blockIdx.x * BN_;

    const __half* gA = A + (size_t)bm * K;
    const __half* gB = B + (size_t)bn * K;

    float c[MF][NF][4];
#pragma unroll
    for (int i = 0; i < MF; i++)
#pragma unroll
        for (int j = 0; j < NF; j++)
#pragma unroll
            for (int k = 0; k < 4; k++) c[i][j][k] = 0.0f;

    const int KT = K / BK;
#pragma unroll
    for (int s = 0; s < NS - 1; s++)
        load_stage<BM_, BN_, K>(sb + s * STAGE, gA + s * BK, gB + s * BK, tid);

    // ---- precomputed ldmatrix offsets (ks enters via XOR of bits 5-6) ----
    const int lrow  = lane & 15;
    const int lhalf = lane >> 4;        // A k half (bit 0 of chunk)
    const int boff  = (lane >> 4) << 3;
    const int bkh   = (lane >> 3) & 1;  // B k half
    uint32_t offA[MF], offB[NF / 2];
#pragma unroll
    for (int mi = 0; mi < MF; mi++) {
        int arow = wm + mi * 16 + lrow;
        offA[mi] = (uint32_t)(arow * 128 + ((lhalf ^ (arow & 7)) << 4));
    }
#pragma unroll
    for (int p = 0; p < NF / 2; p++) {
        int nrow = wn + p * 16 + boff + (lane & 7);
        offB[p] = (uint32_t)(BM_ * 128 + nrow * 128 + ((bkh ^ (nrow & 7)) << 4));
    }

    uint32_t afr[2][MF][4], bfr[2][NF][2];

#define LOAD_FRAGS(ksv, buf)                                                        \
    do {                                                                            \
        const uint32_t xk = (uint32_t)((ksv) << 5);                                 \
        _Pragma("unroll")                                                           \
        for (int p = 0; p < NF / 2; p++)                                            \
            ldsm4(bfr[buf][2 * p][0], bfr[buf][2 * p][1],                           \
                  bfr[buf][2 * p + 1][0], bfr[buf][2 * p + 1][1],                   \
                  (aA + offB[p]) ^ xk);                                             \
        _Pragma("unroll")                                                           \
        for (int mi = 0; mi < MF; mi++)                                             \
            ldsm4(afr[buf][mi][0], afr[buf][mi][1],                                 \
                  afr[buf][mi][2], afr[buf][mi][3],                                 \
                  (aA + offA[mi]) ^ xk);                                            \
    } while (0)

    for (int kt = 0; kt < KT; kt++) {
        asm volatile("cp.async.wait_group %0;\n" :: "n"(NS - 2) : "memory");
        __syncthreads();
        const int nk = kt + NS - 1;
        if (nk < KT)
            load_stage<BM_, BN_, K>(sb + (nk % NS) * STAGE, gA + (size_t)nk * BK,
                                    gB + (size_t)nk * BK, tid);
        else
            asm volatile("cp.async.commit_group;\n" ::: "memory");

        const uint32_t aA = sb + (uint32_t)(kt % NS) * STAGE;

        LOAD_FRAGS(0, 0);
#pragma unroll
        for (int ks = 0; ks < BK / 16; ks++) {
            if (ks + 1 < BK / 16) LOAD_FRAGS(ks + 1, (ks + 1) & 1);
            const int b = ks & 1;
#pragma unroll
            for (int mi = 0; mi < MF; mi++)
#pragma unroll
                for (int ni = 0; ni < NF; ni++)
                    mma16816(c[mi][ni], afr[b][mi], bfr[b][ni]);
        }
    }
#undef LOAD_FRAGS

    // ---------------- epilogue ----------------
    const int g = lane >> 2, t = lane & 3;
#pragma unroll
    for (int mi = 0; mi < MF; mi++) {
#pragma unroll
        for (int ni = 0; ni < NF; ni++) {
            int m0 = bm + wm + mi * 16 + g;
            int n0 = bn + wn + ni * 8 + 2 * t;
            float bv0 = __ldg(bias + n0), bv1 = __ldg(bias + n0 + 1);
            float* cc = c[mi][ni];
#pragma unroll
            for (int half = 0; half < 2; half++) {
                int m = m0 + half * 8;
                float v0 = cc[2 * half + 0] + bv0;
                float v1 = cc[2 * half + 1] + bv1;
                if (FUSE_GELU) {
                    float gl0 = 0.5f * v0 * (1.0f + erff(v0 * 0.70710678118654752f));
                    float gl1 = 0.5f * v1 * (1.0f + erff(v1 * 0.70710678118654752f));
                    *(__half2*)(Oh + (size_t)m * N + n0) =
                        __halves2half2(__float2half_rn(gl0), __float2half_rn(gl1));
                } else {
                    float2 v; v.x = v0; v.y = v1;
                    *(float2*)(Of + (size_t)m * N + n0) = v;
                }
            }
        }
    }
}

// ---------------- launch ----------------
extern "C" void kernel_launch(void* const* d_in, const int* in_sizes, int n_in,
                              void* d_out, int out_size) {
    (void)in_sizes; (void)n_in; (void)out_size;
    const float* x  = (const float*)d_in[0];
    const float* W1 = (const float*)d_in[1];
    const float* b1 = (const float*)d_in[2];
    const float* W2 = (const float*)d_in[3];
    const float* b2 = (const float*)d_in[4];
    float* out = (float*)d_out;

    __half *w1q, *w2q, *xh, *h;
    cudaGetSymbolAddress((void**)&w1q, g_w1q);
    cudaGetSymbolAddress((void**)&w2q, g_w2q);
    cudaGetSymbolAddress((void**)&xh, g_xh);
    cudaGetSymbolAddress((void**)&h, g_h);

    absmean_both<<<1024, 256>>>((const float4*)W1, (const float4*)W2, FF * EMB / 4);
    quantize_both<<<dim3(1024, 2), 256>>>((const float4*)W1, (const float4*)W2,
                                          FF * EMB / 4, (__half2*)w1q, (__half2*)w2q);
    tohalf_kernel<<<1024, 256>>>((const float4*)x, MTOK * EMB / 4, (__half2*)xh);

    constexpr int SMEM1 = NS * (128 + 128) * 128 + 128;   // +128 alignment pad
    constexpr int SMEM2 = NS * (64 + 128) * 128 + 128;
    cudaFuncSetAttribute(ffn_gemm_h<128, 128, FF, EMB, true>,
                         cudaFuncAttributeMaxDynamicSharedMemorySize, SMEM1);
    cudaFuncSetAttribute(ffn_gemm_h<64, 128, EMB, FF, false>,
                         cudaFuncAttributeMaxDynamicSharedMemorySize, SMEM2);

    ffn_gemm_h<128, 128, FF, EMB, true><<<dim3(FF / 128, MTOK / 128), 256, SMEM1>>>(
        xh, w1q, b1, h, nullptr);
    ffn_gemm_h<64, 128, EMB, FF, false><<<dim3(EMB / 128, MTOK / 64), 256, SMEM2>>>(
        h, w2q, b2, nullptr, out);
}

// round 6
// speedup vs baseline: 1.8257x; 1.0398x over previous
#include <cuda_runtime.h>
#include <cuda_fp16.h>
#include <math.h>
#include <stdint.h>

#define EMB 1024
#define FF  4096
#define MTOK 8192

// ---------------- scratch (static device globals; no allocation) ----------------
__device__ __half g_w1q[FF * EMB];
__device__ __half g_w2q[EMB * FF];
__device__ __half g_xh[MTOK * EMB];
__device__ __half g_h[(size_t)MTOK * FF];
__device__ double g_part[2][512];

// ---------------- absmean stage1 (vectorized, both weights, one launch) --------
__global__ void absmean_both(const float4* __restrict__ W1, const float4* __restrict__ W2,
                             int n4) {
    int which = blockIdx.x >> 9;
    int blk = blockIdx.x & 511;
    const float4* W = which ? W2 : W1;
    int tid = threadIdx.x;
    double s = 0.0;
    for (int i = blk * 256 + tid; i < n4; i += 512 * 256) {
        float4 w = W[i];
        s += (double)((fabsf(w.x) + fabsf(w.y)) + (fabsf(w.z) + fabsf(w.w)));
    }
    __shared__ double sm[256];
    sm[tid] = s; __syncthreads();
    for (int o = 128; o > 0; o >>= 1) { if (tid < o) sm[tid] += sm[tid + o]; __syncthreads(); }
    if (tid == 0) g_part[which][blk] = sm[0];
}

// ---------------- ternarize both weights; scale reduced in-kernel --------------
__global__ void quantize_both(const float4* __restrict__ W1, const float4* __restrict__ W2,
                              int n4, __half2* __restrict__ o1, __half2* __restrict__ o2) {
    const int which = blockIdx.y;
    const float4* W = which ? W2 : W1;
    __half2* out = which ? o2 : o1;
    int tid = threadIdx.x;
    __shared__ double sm[256];
    __shared__ float ssc;
    sm[tid] = g_part[which][tid] + g_part[which][tid + 256];
    __syncthreads();
    for (int o = 128; o > 0; o >>= 1) { if (tid < o) sm[tid] += sm[tid + o]; __syncthreads(); }
    if (tid == 0) {
        float mean = (float)(sm[0] / (double)(n4 * 4));
        ssc = 1.0f / fmaxf(mean, 1e-8f);
    }
    __syncthreads();
    const float s = ssc;
    for (int i = blockIdx.x * blockDim.x + tid; i < n4; i += gridDim.x * blockDim.x) {
        float4 w = W[i];
        float q0 = fminf(1.0f, fmaxf(-1.0f, rintf(w.x * s)));
        float q1 = fminf(1.0f, fmaxf(-1.0f, rintf(w.y * s)));
        float q2 = fminf(1.0f, fmaxf(-1.0f, rintf(w.z * s)));
        float q3 = fminf(1.0f, fmaxf(-1.0f, rintf(w.w * s)));
        out[2 * i]     = __halves2half2(__float2half_rn(q0), __float2half_rn(q1));
        out[2 * i + 1] = __halves2half2(__float2half_rn(q2), __float2half_rn(q3));
    }
}

// ---------------- fp32 -> fp16 activation convert ----------------
__global__ void tohalf_kernel(const float4* __restrict__ X, int n4, __half2* __restrict__ o) {
    for (int i = blockIdx.x * blockDim.x + threadIdx.x; i < n4; i += gridDim.x * blockDim.x) {
        float4 f = X[i];
        o[2 * i]     = __halves2half2(__float2half_rn(f.x), __float2half_rn(f.y));
        o[2 * i + 1] = __halves2half2(__float2half_rn(f.z), __float2half_rn(f.w));
    }
}

// ================= HMMA GEMM: C[M,N] = A[M,K] * B[N,K]^T =================
// 128 threads/CTA, 2x2 warp grid, fat warp tiles (BM_/2 x BN_/2).
#define BK 64
#define NS 3

__device__ __forceinline__ void cp16(uint32_t dst, const void* src) {
    asm volatile("cp.async.cg.shared.global [%0], [%1], 16;\n" :: "r"(dst), "l"(src));
}
__device__ __forceinline__ void ldsm4(uint32_t& r0, uint32_t& r1, uint32_t& r2, uint32_t& r3,
                                      uint32_t a) {
    asm volatile("ldmatrix.sync.aligned.m8n8.x4.shared.b16 {%0,%1,%2,%3}, [%4];"
                 : "=r"(r0), "=r"(r1), "=r"(r2), "=r"(r3) : "r"(a));
}
__device__ __forceinline__ void mma16816(float* c, const uint32_t* a, const uint32_t* b) {
    asm volatile("mma.sync.aligned.m16n8k16.row.col.f32.f16.f16.f32 "
                 "{%0,%1,%2,%3}, {%4,%5,%6,%7}, {%8,%9}, {%0,%1,%2,%3};"
                 : "+f"(c[0]), "+f"(c[1]), "+f"(c[2]), "+f"(c[3])
                 : "r"(a[0]), "r"(a[1]), "r"(a[2]), "r"(a[3]), "r"(b[0]), "r"(b[1]));
}

// stage layout: A (BM_*128B) then B (BN_*128B); SW128-style 16B-chunk swizzle
template <int BM_, int BN_, int K>
__device__ __forceinline__ void load_stage(uint32_t sb, const __half* __restrict__ gA,
                                           const __half* __restrict__ gB, int tid) {
    const int chunk = tid & 7;
    const int r0 = tid >> 3;          // 0..15
#pragma unroll
    for (int i = 0; i < BM_ / 16; i++) {
        int row = r0 + i * 16;
        uint32_t so = (uint32_t)(row * 128 + ((chunk ^ (row & 7)) << 4));
        cp16(sb + so, gA + (size_t)row * K + chunk * 8);
    }
#pragma unroll
    for (int i = 0; i < BN_ / 16; i++) {
        int row = r0 + i * 16;
        uint32_t so = (uint32_t)(row * 128 + ((chunk ^ (row & 7)) << 4));
        cp16(sb + (uint32_t)(BM_ * 128) + so, gB + (size_t)row * K + chunk * 8);
    }
    asm volatile("cp.async.commit_group;\n" ::: "memory");
}

template <int BM_, int BN_, int N, int K, bool FUSE_GELU>
__global__ void __launch_bounds__(128)
ffn_gemm_h(const __half* __restrict__ A, const __half* __restrict__ B,
           const float* __restrict__ bias, __half* __restrict__ Oh,
           float* __restrict__ Of) {
    constexpr int MF = BM_ / 2 / 16;             // m16 frags per warp (warp m-tile BM_/2)
    constexpr int NF = BN_ / 2 / 8;              // n8 frags per warp (warp n-tile BN_/2)
    constexpr uint32_t STAGE = (BM_ + BN_) * 128u;
    extern __shared__ char smem_raw[];
    const uint32_t sb = ((uint32_t)__cvta_generic_to_shared(smem_raw) + 127u) & ~127u;
    const int tid = threadIdx.x, lane = tid & 31, warp = tid >> 5;
    const int wm = (warp & 1) * (BM_ / 2);
    const int wn = (warp >> 1) * (BN_ / 2);
    const int bm = blockIdx.y * BM_, bn = blockIdx.x * BN_;

    const __half* gA = A + (size_t)bm * K;
    const __half* gB = B + (size_t)bn * K;

    float c[MF][NF][4];
#pragma unroll
    for (int i = 0; i < MF; i++)
#pragma unroll
        for (int j = 0; j < NF; j++)
#pragma unroll
            for (int k = 0; k < 4; k++) c[i][j][k] = 0.0f;

    const int KT = K / BK;
#pragma unroll
    for (int s = 0; s < NS - 1; s++)
        load_stage<BM_, BN_, K>(sb + s * STAGE, gA + s * BK, gB + s * BK, tid);

    // ---- precomputed ldmatrix offsets (ks enters via XOR of bits 5-6) ----
    const int lrow  = lane & 15;
    const int lhalf = lane >> 4;
    const int boff  = (lane >> 4) << 3;
    const int bkh   = (lane >> 3) & 1;
    uint32_t offA[MF], offB[NF / 2];
#pragma unroll
    for (int mi = 0; mi < MF; mi++) {
        int arow = wm + mi * 16 + lrow;
        offA[mi] = (uint32_t)(arow * 128 + ((lhalf ^ (arow & 7)) << 4));
    }
#pragma unroll
    for (int p = 0; p < NF / 2; p++) {
        int nrow = wn + p * 16 + boff + (lane & 7);
        offB[p] = (uint32_t)(BM_ * 128 + nrow * 128 + ((bkh ^ (nrow & 7)) << 4));
    }

    uint32_t afr[2][MF][4], bfr[2][NF][2];

#define LOAD_FRAGS(ksv, buf)                                                        \
    do {                                                                            \
        const uint32_t xk = (uint32_t)((ksv) << 5);                                 \
        _Pragma("unroll")                                                           \
        for (int p = 0; p < NF / 2; p++)                                            \
            ldsm4(bfr[buf][2 * p][0], bfr[buf][2 * p][1],                           \
                  bfr[buf][2 * p + 1][0], bfr[buf][2 * p + 1][1],                   \
                  (aA + offB[p]) ^ xk);                                             \
        _Pragma("unroll")                                                           \
        for (int mi = 0; mi < MF; mi++)                                             \
            ldsm4(afr[buf][mi][0], afr[buf][mi][1],                                 \
                  afr[buf][mi][2], afr[buf][mi][3],                                 \
                  (aA + offA[mi]) ^ xk);                                            \
    } while (0)

    for (int kt = 0; kt < KT; kt++) {
        asm volatile("cp.async.wait_group %0;\n" :: "n"(NS - 2) : "memory");
        __syncthreads();
        const int nk = kt + NS - 1;
        if (nk < KT)
            load_stage<BM_, BN_, K>(sb + (nk % NS) * STAGE, gA + (size_t)nk * BK,
                                    gB + (size_t)nk * BK, tid);
        else
            asm volatile("cp.async.commit_group;\n" ::: "memory");

        const uint32_t aA = sb + (uint32_t)(kt % NS) * STAGE;

        LOAD_FRAGS(0, 0);
#pragma unroll
        for (int ks = 0; ks < BK / 16; ks++) {
            if (ks + 1 < BK / 16) LOAD_FRAGS(ks + 1, (ks + 1) & 1);
            const int b = ks & 1;
#pragma unroll
            for (int mi = 0; mi < MF; mi++)
#pragma unroll
                for (int ni = 0; ni < NF; ni++)
                    mma16816(c[mi][ni], afr[b][mi], bfr[b][ni]);
        }
    }
#undef LOAD_FRAGS

    // ---------------- epilogue ----------------
    const int g = lane >> 2, t = lane & 3;
#pragma unroll
    for (int mi = 0; mi < MF; mi++) {
#pragma unroll
        for (int ni = 0; ni < NF; ni++) {
            int m0 = bm + wm + mi * 16 + g;
            int n0 = bn + wn + ni * 8 + 2 * t;
            float bv0 = __ldg(bias + n0), bv1 = __ldg(bias + n0 + 1);
            float* cc = c[mi][ni];
#pragma unroll
            for (int half = 0; half < 2; half++) {
                int m = m0 + half * 8;
                float v0 = cc[2 * half + 0] + bv0;
                float v1 = cc[2 * half + 1] + bv1;
                if (FUSE_GELU) {
                    float gl0 = 0.5f * v0 * (1.0f + erff(v0 * 0.70710678118654752f));
                    float gl1 = 0.5f * v1 * (1.0f + erff(v1 * 0.70710678118654752f));
                    *(__half2*)(Oh + (size_t)m * N + n0) =
                        __halves2half2(__float2half_rn(gl0), __float2half_rn(gl1));
                } else {
                    float2 v; v.x = v0; v.y = v1;
                    *(float2*)(Of + (size_t)m * N + n0) = v;
                }
            }
        }
    }
}

// ---------------- launch ----------------
extern "C" void kernel_launch(void* const* d_in, const int* in_sizes, int n_in,
                              void* d_out, int out_size) {
    (void)in_sizes; (void)n_in; (void)out_size;
    const float* x  = (const float*)d_in[0];
    const float* W1 = (const float*)d_in[1];
    const float* b1 = (const float*)d_in[2];
    const float* W2 = (const float*)d_in[3];
    const float* b2 = (const float*)d_in[4];
    float* out = (float*)d_out;

    __half *w1q, *w2q, *xh, *h;
    cudaGetSymbolAddress((void**)&w1q, g_w1q);
    cudaGetSymbolAddress((void**)&w2q, g_w2q);
    cudaGetSymbolAddress((void**)&xh, g_xh);
    cudaGetSymbolAddress((void**)&h, g_h);

    absmean_both<<<1024, 256>>>((const float4*)W1, (const float4*)W2, FF * EMB / 4);
    quantize_both<<<dim3(1024, 2), 256>>>((const float4*)W1, (const float4*)W2,
                                          FF * EMB / 4, (__half2*)w1q, (__half2*)w2q);
    tohalf_kernel<<<1024, 256>>>((const float4*)x, MTOK * EMB / 4, (__half2*)xh);

    constexpr int SMEM1 = NS * (128 + 128) * 128 + 128;   // 98432
    constexpr int SMEM2 = NS * (64 + 128) * 128 + 128;    // 73856
    cudaFuncSetAttribute(ffn_gemm_h<128, 128, FF, EMB, true>,
                         cudaFuncAttributeMaxDynamicSharedMemorySize, SMEM1);
    cudaFuncSetAttribute(ffn_gemm_h<64, 128, EMB, FF, false>,
                         cudaFuncAttributeMaxDynamicSharedMemorySize, SMEM2);

    ffn_gemm_h<128, 128, FF, EMB, true><<<dim3(FF / 128, MTOK / 128), 128, SMEM1>>>(
        xh, w1q, b1, h, nullptr);
    ffn_gemm_h<64, 128, EMB, FF, false><<<dim3(EMB / 128, MTOK / 64), 128, SMEM2>>>(
        h, w2q, b2, nullptr, out);
}

// round 8
// speedup vs baseline: 1.9443x; 1.0650x over previous
#include <cuda_runtime.h>
#include <cuda_fp16.h>
#include <math.h>
#include <stdint.h>

#define EMB 1024
#define FF  4096
#define MTOK 8192

// ---------------- scratch (static device globals; no allocation) ----------------
__device__ __half g_w1q[FF * EMB];
__device__ __half g_w2q[EMB * FF];
__device__ __half g_xh[MTOK * EMB];
__device__ __half g_h[(size_t)MTOK * FF];
__device__ double g_part[2][512];

// ---------------- absmean stage1 (vectorized, both weights, one launch) --------
__global__ void absmean_both(const float4* __restrict__ W1, const float4* __restrict__ W2,
                             int n4) {
    int which = blockIdx.x >> 9;
    int blk = blockIdx.x & 511;
    const float4* W = which ? W2 : W1;
    int tid = threadIdx.x;
    double s = 0.0;
    for (int i = blk * 256 + tid; i < n4; i += 512 * 256) {
        float4 w = W[i];
        s += (double)((fabsf(w.x) + fabsf(w.y)) + (fabsf(w.z) + fabsf(w.w)));
    }
    __shared__ double sm[256];
    sm[tid] = s; __syncthreads();
    for (int o = 128; o > 0; o >>= 1) { if (tid < o) sm[tid] += sm[tid + o]; __syncthreads(); }
    if (tid == 0) g_part[which][blk] = sm[0];
}

// ---------------- ternarize both weights; scale reduced in-kernel --------------
__global__ void quantize_both(const float4* __restrict__ W1, const float4* __restrict__ W2,
                              int n4, __half2* __restrict__ o1, __half2* __restrict__ o2) {
    const int which = blockIdx.y;
    const float4* W = which ? W2 : W1;
    __half2* out = which ? o2 : o1;
    int tid = threadIdx.x;
    __shared__ double sm[256];
    __shared__ float ssc;
    sm[tid] = g_part[which][tid] + g_part[which][tid + 256];
    __syncthreads();
    for (int o = 128; o > 0; o >>= 1) { if (tid < o) sm[tid] += sm[tid + o]; __syncthreads(); }
    if (tid == 0) {
        float mean = (float)(sm[0] / (double)(n4 * 4));
        ssc = 1.0f / fmaxf(mean, 1e-8f);
    }
    __syncthreads();
    const float s = ssc;
    for (int i = blockIdx.x * blockDim.x + tid; i < n4; i += gridDim.x * blockDim.x) {
        float4 w = W[i];
        float q0 = fminf(1.0f, fmaxf(-1.0f, rintf(w.x * s)));
        float q1 = fminf(1.0f, fmaxf(-1.0f, rintf(w.y * s)));
        float q2 = fminf(1.0f, fmaxf(-1.0f, rintf(w.z * s)));
        float q3 = fminf(1.0f, fmaxf(-1.0f, rintf(w.w * s)));
        out[2 * i]     = __halves2half2(__float2half_rn(q0), __float2half_rn(q1));
        out[2 * i + 1] = __halves2half2(__float2half_rn(q2), __float2half_rn(q3));
    }
}

// ---------------- fp32 -> fp16 activation convert ----------------
__global__ void tohalf_kernel(const float4* __restrict__ X, int n4, __half2* __restrict__ o) {
    for (int i = blockIdx.x * blockDim.x + threadIdx.x; i < n4; i += gridDim.x * blockDim.x) {
        float4 f = X[i];
        o[2 * i]     = __halves2half2(__float2half_rn(f.x), __float2half_rn(f.y));
        o[2 * i + 1] = __halves2half2(__float2half_rn(f.z), __float2half_rn(f.w));
    }
}

// ================= HMMA GEMM: C[M,N] = A[M,K] * B[N,K]^T =================
// 128 threads/CTA, 2x2 warp grid, warp tile (BM_/2 x BN_/2). NS pipeline stages.
#define BK 64

__device__ __forceinline__ void cp16(uint32_t dst, const void* src) {
    asm volatile("cp.async.cg.shared.global [%0], [%1], 16;\n" :: "r"(dst), "l"(src));
}
__device__ __forceinline__ void ldsm4(uint32_t& r0, uint32_t& r1, uint32_t& r2, uint32_t& r3,
                                      uint32_t a) {
    asm volatile("ldmatrix.sync.aligned.m8n8.x4.shared.b16 {%0,%1,%2,%3}, [%4];"
                 : "=r"(r0), "=r"(r1), "=r"(r2), "=r"(r3) : "r"(a));
}
__device__ __forceinline__ void mma16816(float* c, const uint32_t* a, const uint32_t* b) {
    asm volatile("mma.sync.aligned.m16n8k16.row.col.f32.f16.f16.f32 "
                 "{%0,%1,%2,%3}, {%4,%5,%6,%7}, {%8,%9}, {%0,%1,%2,%3};"
                 : "+f"(c[0]), "+f"(c[1]), "+f"(c[2]), "+f"(c[3])
                 : "r"(a[0]), "r"(a[1]), "r"(a[2]), "r"(a[3]), "r"(b[0]), "r"(b[1]));
}

// stage layout: A (BM_*128B) then B (BN_*128B); SW128-style 16B-chunk swizzle
template <int BM_, int BN_, int K>
__device__ __forceinline__ void load_stage(uint32_t sb, const __half* __restrict__ gA,
                                           const __half* __restrict__ gB, int tid) {
    const int chunk = tid & 7;
    const int r0 = tid >> 3;          // 0..15
#pragma unroll
    for (int i = 0; i < BM_ / 16; i++) {
        int row = r0 + i * 16;
        uint32_t so = (uint32_t)(row * 128 + ((chunk ^ (row & 7)) << 4));
        cp16(sb + so, gA + (size_t)row * K + chunk * 8);
    }
#pragma unroll
    for (int i = 0; i < BN_ / 16; i++) {
        int row = r0 + i * 16;
        uint32_t so = (uint32_t)(row * 128 + ((chunk ^ (row & 7)) << 4));
        cp16(sb + (uint32_t)(BM_ * 128) + so, gB + (size_t)row * K + chunk * 8);
    }
    asm volatile("cp.async.commit_group;\n" ::: "memory");
}

template <int BM_, int BN_, int NS, int N, int K, bool FUSE_GELU>
__global__ void __launch_bounds__(128, 3)
ffn_gemm_h(const __half* __restrict__ A, const __half* __restrict__ B,
           const float* __restrict__ bias, __half* __restrict__ Oh,
           float* __restrict__ Of) {
    constexpr int MF = BM_ / 2 / 16;             // m16 frags per warp
    constexpr int NF = BN_ / 2 / 8;              // n8 frags per warp
    constexpr uint32_t STAGE = (BM_ + BN_) * 128u;
    extern __shared__ char smem_raw[];
    const uint32_t sb = ((uint32_t)__cvta_generic_to_shared(smem_raw) + 127u) & ~127u;
    const int tid = threadIdx.x, lane = tid & 31, warp = tid >> 5;
    const int wm = (warp & 1) * (BM_ / 2);
    const int wn = (warp >> 1) * (BN_ / 2);
    const int bm = blockIdx.y * BM_, bn = blockIdx.x * BN_;

    const __half* gA = A + (size_t)bm * K;
    const __half* gB = B + (size_t)bn * K;

    float c[MF][NF][4];
#pragma unroll
    for (int i = 0; i < MF; i++)
#pragma unroll
        for (int j = 0; j < NF; j++)
#pragma unroll
            for (int k = 0; k < 4; k++) c[i][j][k] = 0.0f;

    const int KT = K / BK;
#pragma unroll
    for (int s = 0; s < NS - 1; s++)
        load_stage<BM_, BN_, K>(sb + s * STAGE, gA + s * BK, gB + s * BK, tid);

    // ---- precomputed ldmatrix offsets (ks enters via XOR of bits 5-6) ----
    const int lrow  = lane & 15;
    const int lhalf = lane >> 4;
    const int boff  = (lane >> 4) << 3;
    const int bkh   = (lane >> 3) & 1;
    uint32_t offA[MF], offB[NF / 2];
#pragma unroll
    for (int mi = 0; mi < MF; mi++) {
        int arow = wm + mi * 16 + lrow;
        offA[mi] = (uint32_t)(arow * 128 + ((lhalf ^ (arow & 7)) << 4));
    }
#pragma unroll
    for (int p = 0; p < NF / 2; p++) {
        int nrow = wn + p * 16 + boff + (lane & 7);
        offB[p] = (uint32_t)(BM_ * 128 + nrow * 128 + ((bkh ^ (nrow & 7)) << 4));
    }

    uint32_t afr[MF][4], bfr[NF][2];

    for (int kt = 0; kt < KT; kt++) {
        asm volatile("cp.async.wait_group %0;\n" :: "n"(NS - 2) : "memory");
        __syncthreads();
        const int nk = kt + NS - 1;
        if (nk < KT)
            load_stage<BM_, BN_, K>(sb + (nk % NS) * STAGE, gA + (size_t)nk * BK,
                                    gB + (size_t)nk * BK, tid);
        else
            asm volatile("cp.async.commit_group;\n" ::: "memory");

        const uint32_t aA = sb + (uint32_t)(kt % NS) * STAGE;

#pragma unroll
        for (int ks = 0; ks < BK / 16; ks++) {
            const uint32_t xk = (uint32_t)(ks << 5);
#pragma unroll
            for (int p = 0; p < NF / 2; p++)
                ldsm4(bfr[2 * p][0], bfr[2 * p][1], bfr[2 * p + 1][0], bfr[2 * p + 1][1],
                      (aA + offB[p]) ^ xk);
#pragma unroll
            for (int mi = 0; mi < MF; mi++)
                ldsm4(afr[mi][0], afr[mi][1], afr[mi][2], afr[mi][3],
                      (aA + offA[mi]) ^ xk);
#pragma unroll
            for (int mi = 0; mi < MF; mi++)
#pragma unroll
                for (int ni = 0; ni < NF; ni++)
                    mma16816(c[mi][ni], afr[mi], bfr[ni]);
        }
    }

    // ---------------- epilogue ----------------
    const int g = lane >> 2, t = lane & 3;
#pragma unroll
    for (int mi = 0; mi < MF; mi++) {
#pragma unroll
        for (int ni = 0; ni < NF; ni++) {
            int m0 = bm + wm + mi * 16 + g;
            int n0 = bn + wn + ni * 8 + 2 * t;
            float bv0 = __ldg(bias + n0), bv1 = __ldg(bias + n0 + 1);
            float* cc = c[mi][ni];
#pragma unroll
            for (int half = 0; half < 2; half++) {
                int m = m0 + half * 8;
                float v0 = cc[2 * half + 0] + bv0;
                float v1 = cc[2 * half + 1] + bv1;
                if (FUSE_GELU) {
                    float gl0 = 0.5f * v0 * (1.0f + erff(v0 * 0.70710678118654752f));
                    float gl1 = 0.5f * v1 * (1.0f + erff(v1 * 0.70710678118654752f));
                    *(__half2*)(Oh + (size_t)m * N + n0) =
                        __halves2half2(__float2half_rn(gl0), __float2half_rn(gl1));
                } else {
                    float2 v; v.x = v0; v.y = v1;
                    *(float2*)(Of + (size_t)m * N + n0) = v;
                }
            }
        }
    }
}

// ---------------- launch ----------------
extern "C" void kernel_launch(void* const* d_in, const int* in_sizes, int n_in,
                              void* d_out, int out_size) {
    (void)in_sizes; (void)n_in; (void)out_size;
    const float* x  = (const float*)d_in[0];
    const float* W1 = (const float*)d_in[1];
    const float* b1 = (const float*)d_in[2];
    const float* W2 = (const float*)d_in[3];
    const float* b2 = (const float*)d_in[4];
    float* out = (float*)d_out;

    __half *w1q, *w2q, *xh, *h;
    cudaGetSymbolAddress((void**)&w1q, g_w1q);
    cudaGetSymbolAddress((void**)&w2q, g_w2q);
    cudaGetSymbolAddress((void**)&xh, g_xh);
    cudaGetSymbolAddress((void**)&h, g_h);

    absmean_both<<<1024, 256>>>((const float4*)W1, (const float4*)W2, FF * EMB / 4);
    quantize_both<<<dim3(1024, 2), 256>>>((const float4*)W1, (const float4*)W2,
                                          FF * EMB / 4, (__half2*)w1q, (__half2*)w2q);
    tohalf_kernel<<<1024, 256>>>((const float4*)x, MTOK * EMB / 4, (__half2*)xh);

    // G1: 128x128 tile, NS=2 (64KB/CTA -> 3 CTAs/SM). G2: 64x128 tile, NS=3 (72KB -> 3 CTAs/SM).
    constexpr int SMEM1 = 2 * (128 + 128) * 128 + 128;   // 65664
    constexpr int SMEM2 = 3 * (64 + 128) * 128 + 128;    // 73856
    cudaFuncSetAttribute(ffn_gemm_h<128, 128, 2, FF, EMB, true>,
                         cudaFuncAttributeMaxDynamicSharedMemorySize, SMEM1);
    cudaFuncSetAttribute(ffn_gemm_h<64, 128, 3, EMB, FF, false>,
                         cudaFuncAttributeMaxDynamicSharedMemorySize, SMEM2);

    ffn_gemm_h<128, 128, 2, FF, EMB, true><<<dim3(FF / 128, MTOK / 128), 128, SMEM1>>>(
        xh, w1q, b1, h, nullptr);
    ffn_gemm_h<64, 128, 3, EMB, FF, false><<<dim3(EMB / 128, MTOK / 64), 128, SMEM2>>>(
        h, w2q, b2, nullptr, out);
}